// round 6
// baseline (speedup 1.0000x reference)
#include <cuda_runtime.h>
#include <cuda_bf16.h>
#include <math.h>
#include <stdint.h>

#define Bn 64
#define Sn 1024
#define In 256
#define Hn 256
#define Gn 768   // 3*H

// Scratch for input-side gate projections xg[B][S][768] (reused by both layers).
__device__ float g_xg[(size_t)Bn * Sn * Gn];

// ---------------------------------------------------------------------------
// GEMM: C[m][n] = sum_k X[m][k] * W[n][k] + bias[n]
//   M = 65536 (b*S+s), N = 768, K = 256.  X row pitch = lda. C = g_xg (pitch 768).
// 64x64 tile, 256 threads, 4x4 register fragments, K chunked by 64.
// ---------------------------------------------------------------------------
__global__ void gemm768_kernel(const float* __restrict__ X, int lda,
                               const float* __restrict__ W,
                               const float* __restrict__ bias)
{
    __shared__ float Xs[64][68];
    __shared__ float Ws[64][68];

    const int tid = threadIdx.x;
    const int tx = tid & 15;       // n dimension
    const int ty = tid >> 4;       // m dimension
    const int m0 = blockIdx.y * 64;
    const int n0 = blockIdx.x * 64;

    const int kq = tid & 15;       // loader: k quad
    const int rr = tid >> 4;       // loader: row

    float acc[4][4] = {};

    for (int kc = 0; kc < 256; kc += 64) {
#pragma unroll
        for (int jj = 0; jj < 4; jj++) {
            int row = rr + 16 * jj;
            *(float4*)&Xs[row][kq * 4] =
                *(const float4*)&X[(size_t)(m0 + row) * lda + kc + kq * 4];
            *(float4*)&Ws[row][kq * 4] =
                *(const float4*)&W[(size_t)(n0 + row) * 256 + kc + kq * 4];
        }
        __syncthreads();

#pragma unroll 8
        for (int k = 0; k < 64; k++) {
            float xf[4], wf[4];
#pragma unroll
            for (int jj = 0; jj < 4; jj++) xf[jj] = Xs[ty + 16 * jj][k];
#pragma unroll
            for (int ii = 0; ii < 4; ii++) wf[ii] = Ws[tx + 16 * ii][k];
#pragma unroll
            for (int jj = 0; jj < 4; jj++)
#pragma unroll
                for (int ii = 0; ii < 4; ii++)
                    acc[jj][ii] += xf[jj] * wf[ii];
        }
        __syncthreads();
    }

#pragma unroll
    for (int jj = 0; jj < 4; jj++) {
        int m = m0 + ty + 16 * jj;
#pragma unroll
        for (int ii = 0; ii < 4; ii++) {
            int n = n0 + tx + 16 * ii;
            g_xg[(size_t)m * Gn + n] = acc[jj][ii] + bias[n];
        }
    }
}

// ---------------------------------------------------------------------------
// Recurrence kernel.
// Cluster of 4 CTAs handles 2 batch rows; 32 clusters x 4 = 128 CTAs.
// CTA rank r owns hidden columns [r*64, r*64+64). It holds the 192 W_hh rows
// {cols, 256+cols, 512+cols} resident in SMEM (fp32, pitch 260) for all steps.
// 384 threads: tid%192 = local gate-row, tid/192 = k-half (128 k each).
// h (256 floats x 2 batch) is replicated in each CTA, double-buffered;
// new h slices are broadcast via st.shared::cluster, ordered by barrier.cluster.
// ---------------------------------------------------------------------------
// smem layout (floats): Wr[192*260] | hb[2*2*256] | pacc[2*192*2] | bh[192]
#define SM_WR   0
#define SM_HB   (192 * 260)
#define SM_PACC (SM_HB + 1024)
#define SM_BH   (SM_PACC + 768)
#define SM_TOT  (SM_BH + 192)            // 51904 floats = 207616 bytes

__global__ void __cluster_dims__(4, 1, 1) __launch_bounds__(384, 1)
gru_rec_kernel(const float* __restrict__ Whh,   // [768][256]
               const float* __restrict__ bhh,   // [768]
               float* __restrict__ outA, int pitchA, int colOffA,  // always written
               float* __restrict__ outB)        // second copy (pitch Hn) or null
{
    extern __shared__ float smem[];
    float* Wr   = smem + SM_WR;
    float* hb   = smem + SM_HB;
    float* pacc = smem + SM_PACC;
    float* bh   = smem + SM_BH;

    const int tid = threadIdx.x;
    uint32_t rank;
    asm("mov.u32 %0, %%cluster_ctarank;" : "=r"(rank));
    const int cid   = blockIdx.x >> 2;
    const int b0    = cid * 2;            // two batch rows per cluster
    const int cbase = (int)rank * 64;     // owned hidden-column base

    // ---- load resident weights (global gate-row g for local row l) ----
    for (int idx = tid; idx < 192 * 256; idx += 384) {
        int l = idx >> 8, k = idx & 255;
        int g = (l < 64) ? (cbase + l)
              : (l < 128) ? (256 + cbase + (l - 64))
                          : (512 + cbase + (l - 128));
        Wr[l * 260 + k] = Whh[(size_t)g * 256 + k];
    }
    for (int l = tid; l < 192; l += 384) {
        int g = (l < 64) ? (cbase + l)
              : (l < 128) ? (256 + cbase + (l - 64))
                          : (512 + cbase + (l - 128));
        bh[l] = bhh[g];
    }
    for (int i = tid; i < 1024; i += 384) hb[i] = 0.0f;   // h0 = 0, both buffers
    __syncthreads();

    // remote hb base addresses for all 4 cluster ranks
    uint32_t hb_local = (uint32_t)__cvta_generic_to_shared(hb);
    uint32_t remote_hb[4];
#pragma unroll
    for (int r2 = 0; r2 < 4; r2++) {
        uint32_t ra;
        asm("mapa.shared::cluster.u32 %0, %1, %2;" : "=r"(ra) : "r"(hb_local), "r"(r2));
        remote_hb[r2] = ra;
    }

    // everyone's hb must be zeroed before anyone can write remote h_new
    asm volatile("barrier.cluster.arrive.aligned;" ::: "memory");
    asm volatile("barrier.cluster.wait.aligned;"   ::: "memory");

    const int l   = tid % 192;
    const int kb  = tid / 192;            // 0 or 1
    const int kst = kb * 128;
    const float* wrow = Wr + l * 260 + kst;

    const int j    = tid & 63;            // gate threads (tid<128)
    const int bsel = (tid >> 6) & 1;

    for (int t = 0; t < Sn; t++) {
        const int cur = t & 1;
        const int nxt = cur ^ 1;

        // prefetch input-side gates for this step (long-latency, overlapped)
        float xr = 0.f, xz = 0.f, xn = 0.f;
        if (tid < 128) {
            const float* xp = g_xg + (((size_t)(b0 + bsel)) * Sn + t) * Gn;
            xr = __ldg(xp + cbase + j);
            xz = __ldg(xp + 256 + cbase + j);
            xn = __ldg(xp + 512 + cbase + j);
        }

        // ---- dot: hg_partial[l][b] over this thread's 128-k half ----
        const float* h0p = hb + cur * 512 + kst;        // batch 0
        const float* h1p = hb + cur * 512 + 256 + kst;  // batch 1
        float a0 = 0.f, a1 = 0.f, c0 = 0.f, c1 = 0.f;
#pragma unroll 8
        for (int kk = 0; kk < 128; kk += 4) {
            float4 w  = *(const float4*)(wrow + kk);
            float4 h0 = *(const float4*)(h0p + kk);
            float4 h1 = *(const float4*)(h1p + kk);
            a0 += w.x * h0.x + w.y * h0.y;
            a1 += w.z * h0.z + w.w * h0.w;
            c0 += w.x * h1.x + w.y * h1.y;
            c1 += w.z * h1.z + w.w * h1.w;
        }
        pacc[(kb * 192 + l) * 2 + 0] = a0 + a1;
        pacc[(kb * 192 + l) * 2 + 1] = c0 + c1;
        __syncthreads();

        // ---- gates + state update (128 threads: 64 cols x 2 batch) ----
        if (tid < 128) {
            float hr = pacc[(j)       * 2 + bsel] + pacc[(192 + j)       * 2 + bsel] + bh[j];
            float hz = pacc[(64 + j)  * 2 + bsel] + pacc[(192 + 64 + j)  * 2 + bsel] + bh[64 + j];
            float hn = pacc[(128 + j) * 2 + bsel] + pacc[(192 + 128 + j) * 2 + bsel] + bh[128 + j];

            float r = 1.0f / (1.0f + __expf(-(xr + hr)));
            float z = 1.0f / (1.0f + __expf(-(xz + hz)));
            float n = tanhf(xn + r * hn);

            int gcol = cbase + j;
            float hold = hb[cur * 512 + bsel * 256 + gcol];
            float hnew = (1.0f - z) * n + z * hold;

            size_t row = ((size_t)(b0 + bsel)) * Sn + t;
            outA[row * pitchA + colOffA + gcol] = hnew;
            if (outB) outB[row * Hn + gcol] = hnew;

            // broadcast h_new to all 4 CTAs' next-buffer
            uint32_t off = (uint32_t)((nxt * 512 + bsel * 256 + gcol) * 4);
#pragma unroll
            for (int r2 = 0; r2 < 4; r2++) {
                asm volatile("st.shared::cluster.f32 [%0], %1;"
                             :: "r"(remote_hb[r2] + off), "f"(hnew));
            }
        }

        // release h_new to the cluster; acquire everyone else's slices
        asm volatile("barrier.cluster.arrive.aligned;" ::: "memory");
        asm volatile("barrier.cluster.wait.aligned;"   ::: "memory");
    }
}

// ---------------------------------------------------------------------------
// Launch: GEMM0 -> REC0 -> GEMM1 -> REC1 on the default stream.
// Output layout (tuple flattened): [ h2 (B,S,H) | concat(h1,h2) (B,S,2H) ].
// ---------------------------------------------------------------------------
extern "C" void kernel_launch(void* const* d_in, const int* in_sizes, int n_in,
                              void* d_out, int out_size)
{
    const float* inputs = (const float*)d_in[0];
    const float* W_ih0  = (const float*)d_in[1];
    const float* W_hh0  = (const float*)d_in[2];
    const float* b_ih0  = (const float*)d_in[3];
    const float* b_hh0  = (const float*)d_in[4];
    const float* W_ih1  = (const float*)d_in[5];
    const float* W_hh1  = (const float*)d_in[6];
    const float* b_ih1  = (const float*)d_in[7];
    const float* b_hh1  = (const float*)d_in[8];

    float* out    = (float*)d_out;
    float* h2     = out;                              // [B,S,H]
    float* concat = out + (size_t)Bn * Sn * Hn;       // [B,S,2H]

    (void)in_sizes; (void)n_in; (void)out_size;

    const int REC_SMEM = SM_TOT * 4;  // 207616 bytes
    cudaFuncSetAttribute(gru_rec_kernel,
                         cudaFuncAttributeMaxDynamicSharedMemorySize, REC_SMEM);

    dim3 ggrid(Gn / 64, (Bn * Sn) / 64);   // 12 x 1024

    // Layer 0
    gemm768_kernel<<<ggrid, 256>>>(inputs, In, W_ih0, b_ih0);
    // h1 -> concat[:, :, 0:256] (pitch 512)
    gru_rec_kernel<<<128, 384, REC_SMEM>>>(W_hh0, b_hh0, concat, 2 * Hn, 0, nullptr);

    // Layer 1: input is h1 living in concat (row pitch 512, cols 0..255)
    gemm768_kernel<<<ggrid, 256>>>(concat, 2 * Hn, W_ih1, b_ih1);
    // h2 -> concat[:, :, 256:512] and h2 buffer
    gru_rec_kernel<<<128, 384, REC_SMEM>>>(W_hh1, b_hh1, concat, 2 * Hn, Hn, h2);
}

// round 7
// speedup vs baseline: 1.0878x; 1.0878x over previous
#include <cuda_runtime.h>
#include <cuda_bf16.h>
#include <math.h>
#include <stdint.h>

#define Bn 64
#define Sn 1024
#define In 256
#define Hn 256
#define Gn 768   // 3*H

// packed f32x2 FMA (sm_103a): d = a*b + c elementwise on packed fp32 pairs
#define FMA2(d, a, b, c) \
    asm("fma.rn.f32x2 %0, %1, %2, %3;" : "=l"(d) : "l"(a), "l"(b), "l"(c))
#define ADD2(d, a, b) \
    asm("add.rn.f32x2 %0, %1, %2;" : "=l"(d) : "l"(a), "l"(b))
#define UNPK(lo, hi, v) \
    asm("mov.b64 {%0,%1}, %2;" : "=f"(lo), "=f"(hi) : "l"(v))

// Scratch for input-side gate projections xg[B][S][768] (reused by both layers).
__device__ float g_xg[(size_t)Bn * Sn * Gn];

// ---------------------------------------------------------------------------
// GEMM: C[m][n] = sum_k X[m][k]*W[n][k] + bias[n];  M=65536, N=768, K=256.
// 64x64 tile, 256 threads, 4x4 fragments, k processed as f32x2 pairs.
// SMEM pitch 70 floats: 64-bit fragment loads are bank-conflict-free
// (bank step 6 per row -> 16 distinct rows hit 16 distinct banks).
// ---------------------------------------------------------------------------
__global__ void __launch_bounds__(256)
gemm768_kernel(const float* __restrict__ X, int lda,
               const float* __restrict__ W,
               const float* __restrict__ bias)
{
    __shared__ __align__(16) float Xs[64 * 70];
    __shared__ __align__(16) float Ws[64 * 70];

    const int tid = threadIdx.x;
    const int tx = tid & 15;       // n dimension
    const int ty = tid >> 4;       // m dimension
    const int m0 = blockIdx.y * 64;
    const int n0 = blockIdx.x * 64;

    const int kq = tid & 15;       // loader: k quad
    const int rr = tid >> 4;       // loader: row

    uint64_t acc[4][4] = {};       // f32x2 accumulators (even-k, odd-k partials)

    for (int kc = 0; kc < 256; kc += 64) {
#pragma unroll
        for (int jj = 0; jj < 4; jj++) {
            int row = rr + 16 * jj;
            float4 xv = *(const float4*)&X[(size_t)(m0 + row) * lda + kc + kq * 4];
            float4 wv = *(const float4*)&W[(size_t)(n0 + row) * 256 + kc + kq * 4];
            // pitch-70 rows: 16B-misaligned, store as two 8B chunks
            *(float2*)&Xs[row * 70 + kq * 4]     = make_float2(xv.x, xv.y);
            *(float2*)&Xs[row * 70 + kq * 4 + 2] = make_float2(xv.z, xv.w);
            *(float2*)&Ws[row * 70 + kq * 4]     = make_float2(wv.x, wv.y);
            *(float2*)&Ws[row * 70 + kq * 4 + 2] = make_float2(wv.z, wv.w);
        }
        __syncthreads();

#pragma unroll 8
        for (int kp = 0; kp < 32; kp++) {      // 32 k-pairs per chunk
            uint64_t xf[4], wf[4];
#pragma unroll
            for (int jj = 0; jj < 4; jj++)
                xf[jj] = *(const uint64_t*)&Xs[(ty + 16 * jj) * 70 + 2 * kp];
#pragma unroll
            for (int ii = 0; ii < 4; ii++)
                wf[ii] = *(const uint64_t*)&Ws[(tx + 16 * ii) * 70 + 2 * kp];
#pragma unroll
            for (int jj = 0; jj < 4; jj++)
#pragma unroll
                for (int ii = 0; ii < 4; ii++)
                    FMA2(acc[jj][ii], xf[jj], wf[ii], acc[jj][ii]);
        }
        __syncthreads();
    }

#pragma unroll
    for (int jj = 0; jj < 4; jj++) {
        int m = m0 + ty + 16 * jj;
#pragma unroll
        for (int ii = 0; ii < 4; ii++) {
            int n = n0 + tx + 16 * ii;
            float lo, hi;
            UNPK(lo, hi, acc[jj][ii]);
            g_xg[(size_t)m * Gn + n] = lo + hi + bias[n];
        }
    }
}

// ---------------------------------------------------------------------------
// Recurrence kernel. Cluster of 4 CTAs = 2 batch rows; 32 clusters = 128 CTAs.
// CTA rank r owns hidden cols [r*64, r*64+64): its 192 gate rows of W_hh live
// ENTIRELY IN REGISTERS (64 x b64 per thread). 384 threads: l = tid%192 gate
// row, kb = tid/192 selects the 128-k half. h kept in SMEM (double-buffered,
// broadcast reads), new h broadcast to the cluster via st.shared::cluster.
// Dot products use packed fma.rn.f32x2 over natural k-pairs.
// ---------------------------------------------------------------------------
__global__ void __cluster_dims__(4, 1, 1) __launch_bounds__(384, 1)
gru_rec_kernel(const float* __restrict__ Whh,   // [768][256]
               const float* __restrict__ bhh,   // [768]
               float* __restrict__ outA, int pitchA, int colOffA,
               float* __restrict__ outB)        // second copy (pitch Hn) or null
{
    __shared__ __align__(16) float hb[2 * 2 * 256];  // [buf][batch][k]
    __shared__ float pacc[2 * 192 * 2];              // [kb][l][batch]
    __shared__ float bh[192];

    const int tid = threadIdx.x;
    uint32_t rank;
    asm("mov.u32 %0, %%cluster_ctarank;" : "=r"(rank));
    const int cid   = blockIdx.x >> 2;
    const int b0    = cid * 2;
    const int cbase = (int)rank * 64;

    const int l   = tid % 192;
    const int kb  = tid / 192;            // 0 or 1
    const int kst = kb * 128;
    const int g   = (l < 64) ? (cbase + l)
                  : (l < 128) ? (256 + cbase + (l - 64))
                              : (512 + cbase + (l - 128));

    // ---- weights -> registers (64 x b64 = 128 floats per thread) ----
    uint64_t w[64];
    {
        const uint64_t* wsrc = (const uint64_t*)(Whh + (size_t)g * 256 + kst);
#pragma unroll
        for (int i = 0; i < 64; i++) w[i] = wsrc[i];
    }

    if (tid < 192) bh[l] = bhh[g];
    for (int i = tid; i < 1024; i += 384) hb[i] = 0.0f;   // h0 = 0, both bufs
    __syncthreads();

    // remote hb base addresses for all 4 cluster ranks
    uint32_t hb_local = (uint32_t)__cvta_generic_to_shared(hb);
    uint32_t remote_hb[4];
#pragma unroll
    for (int r2 = 0; r2 < 4; r2++) {
        uint32_t ra;
        asm("mapa.shared::cluster.u32 %0, %1, %2;" : "=r"(ra) : "r"(hb_local), "r"(r2));
        remote_hb[r2] = ra;
    }

    // everyone's hb must be zeroed before anyone writes remote h_new
    asm volatile("barrier.cluster.arrive.aligned;" ::: "memory");
    asm volatile("barrier.cluster.wait.aligned;"   ::: "memory");

    // writer-thread (tid<128) precomputed pointers
    const int j    = tid & 63;
    const int bsel = (tid >> 6) & 1;
    const int gcol = cbase + j;
    const float* xp = g_xg + ((size_t)(b0 + bsel) * Sn) * Gn + gcol;
    float* oA = outA + ((size_t)(b0 + bsel) * Sn) * pitchA + colOffA + gcol;
    float* oB = outB ? outB + ((size_t)(b0 + bsel) * Sn) * Hn + gcol : nullptr;

    for (int t = 0; t < Sn; t++) {
        const int cur = t & 1;
        const int nxt = cur ^ 1;

        // prefetch input-side gates (global, latency hidden under dot loop)
        float xr = 0.f, xz = 0.f, xn = 0.f;
        if (tid < 128) {
            xr = __ldg(xp);
            xz = __ldg(xp + 256);
            xn = __ldg(xp + 512);
        }

        // ---- packed dot: this thread's 128-k half, both batch rows ----
        const ulonglong2* h0p = (const ulonglong2*)(hb + cur * 512 + kst);
        const ulonglong2* h1p = (const ulonglong2*)(hb + cur * 512 + 256 + kst);
        uint64_t a0 = 0, a1 = 0, c0 = 0, c1 = 0;
#pragma unroll
        for (int i = 0; i < 32; i++) {
            ulonglong2 hA = h0p[i];           // 4 h values, batch 0 (broadcast)
            ulonglong2 hB = h1p[i];           // 4 h values, batch 1
            FMA2(a0, w[2 * i],     hA.x, a0);
            FMA2(a1, w[2 * i + 1], hA.y, a1);
            FMA2(c0, w[2 * i],     hB.x, c0);
            FMA2(c1, w[2 * i + 1], hB.y, c1);
        }
        uint64_t s0, s1;
        ADD2(s0, a0, a1);
        ADD2(s1, c0, c1);
        float s0l, s0h, s1l, s1h;
        UNPK(s0l, s0h, s0);
        UNPK(s1l, s1h, s1);
        pacc[(kb * 192 + l) * 2 + 0] = s0l + s0h;
        pacc[(kb * 192 + l) * 2 + 1] = s1l + s1h;
        __syncthreads();

        // ---- gates + state update (128 threads: 64 cols x 2 batch) ----
        if (tid < 128) {
            float hr = pacc[(j)       * 2 + bsel] + pacc[(192 + j)       * 2 + bsel] + bh[j];
            float hz = pacc[(64 + j)  * 2 + bsel] + pacc[(192 + 64 + j)  * 2 + bsel] + bh[64 + j];
            float hn = pacc[(128 + j) * 2 + bsel] + pacc[(192 + 128 + j) * 2 + bsel] + bh[128 + j];

            float r = 1.0f / (1.0f + __expf(-(xr + hr)));
            float z = 1.0f / (1.0f + __expf(-(xz + hz)));
            float n = tanhf(xn + r * hn);

            float hold = hb[cur * 512 + bsel * 256 + gcol];
            float hnew = (1.0f - z) * n + z * hold;

            *oA = hnew;
            if (oB) { *oB = hnew; oB += Hn; }

            // broadcast h_new to all 4 CTAs' next buffer
            uint32_t off = (uint32_t)((nxt * 512 + bsel * 256 + gcol) * 4);
#pragma unroll
            for (int r2 = 0; r2 < 4; r2++) {
                asm volatile("st.shared::cluster.f32 [%0], %1;"
                             :: "r"(remote_hb[r2] + off), "f"(hnew));
            }
            xp += Gn;
            oA += pitchA;
        }

        // release h_new to the cluster; acquire everyone else's slices
        asm volatile("barrier.cluster.arrive.aligned;" ::: "memory");
        asm volatile("barrier.cluster.wait.aligned;"   ::: "memory");
    }
}

// ---------------------------------------------------------------------------
// Launch: GEMM0 -> REC0 -> GEMM1 -> REC1.
// Output layout (tuple flattened): [ h2 (B,S,H) | concat(h1,h2) (B,S,2H) ].
// ---------------------------------------------------------------------------
extern "C" void kernel_launch(void* const* d_in, const int* in_sizes, int n_in,
                              void* d_out, int out_size)
{
    const float* inputs = (const float*)d_in[0];
    const float* W_ih0  = (const float*)d_in[1];
    const float* W_hh0  = (const float*)d_in[2];
    const float* b_ih0  = (const float*)d_in[3];
    const float* b_hh0  = (const float*)d_in[4];
    const float* W_ih1  = (const float*)d_in[5];
    const float* W_hh1  = (const float*)d_in[6];
    const float* b_ih1  = (const float*)d_in[7];
    const float* b_hh1  = (const float*)d_in[8];

    float* out    = (float*)d_out;
    float* h2     = out;                              // [B,S,H]
    float* concat = out + (size_t)Bn * Sn * Hn;       // [B,S,2H]

    (void)in_sizes; (void)n_in; (void)out_size;

    dim3 ggrid(Gn / 64, (Bn * Sn) / 64);   // 12 x 1024

    // Layer 0
    gemm768_kernel<<<ggrid, 256>>>(inputs, In, W_ih0, b_ih0);
    gru_rec_kernel<<<128, 384>>>(W_hh0, b_hh0, concat, 2 * Hn, 0, nullptr);

    // Layer 1: input is h1 living in concat (row pitch 512, cols 0..255)
    gemm768_kernel<<<ggrid, 256>>>(concat, 2 * Hn, W_ih1, b_ih1);
    gru_rec_kernel<<<128, 384>>>(W_hh1, b_hh1, concat, 2 * Hn, Hn, h2);
}